// round 1
// baseline (speedup 1.0000x reference)
#include <cuda_runtime.h>
#include <math.h>
#include <stdint.h>

// Problem constants (match reference_code)
#define N_HITS 200000
#define DIM 8
#define P_IDS 512
#define NCLUST 511          // nonzero particle ids 1..511
#define Q_MIN 0.01f

// ---------------------------------------------------------------------------
// Device scratch (no allocations allowed -> __device__ globals)
// ---------------------------------------------------------------------------
__device__ double g_sum;
__device__ unsigned long long g_best[P_IDS];      // packed (q_bits<<32) | (~idx)
// rep layout per cluster: [0]=(-2*xa[0..3]) [1]=(-2*xa[4..7]) [2]=(xa_sq, q_a, 0, 0)
__device__ float4 g_rep[NCLUST * 3];

__device__ __forceinline__ float compute_q(float beta) {
    float a = atanhf(beta);
    return fmaf(a, a, Q_MIN);
}

// ---------------------------------------------------------------------------
// Kernel 0: zero scratch (graph replays must be idempotent)
// ---------------------------------------------------------------------------
__global__ void k_init() {
    int t = blockIdx.x * blockDim.x + threadIdx.x;
    if (t == 0) g_sum = 0.0;
    if (t < P_IDS) g_best[t] = 0ull;
}

// ---------------------------------------------------------------------------
// Kernel 1: per-cluster argmax of q via packed atomicMax.
// q >= 0.01 > 0, so IEEE float bits are monotone as unsigned.
// Index stored complemented so that for (astronomically unlikely) q ties,
// the LOWER index wins, matching jnp.argmax tie-breaking.
// ---------------------------------------------------------------------------
__global__ void k_argmax(const float* __restrict__ beta,
                         const int* __restrict__ pid) {
    int i = blockIdx.x * blockDim.x + threadIdx.x;
    if (i >= N_HITS) return;
    int p = pid[i];
    if (p == 0) return;                       // noise hits excluded
    float q = compute_q(beta[i]);
    unsigned long long packed =
        ((unsigned long long)__float_as_uint(q) << 32) |
        (unsigned long long)(0xFFFFFFFFu - (unsigned)i);
    atomicMax(&g_best[p], packed);
}

// ---------------------------------------------------------------------------
// Kernel 2: gather representative data for the 511 clusters.
// Empty cluster -> packed==0 -> index 0 (matches jnp.argmax over all -inf).
// ---------------------------------------------------------------------------
__global__ void k_gather(const float* __restrict__ beta,
                         const float* __restrict__ x) {
    int p = blockIdx.x * blockDim.x + threadIdx.x;   // 0..510 -> pid p+1
    if (p >= NCLUST) return;
    unsigned long long packed = g_best[p + 1];
    int idx = (packed == 0ull)
                  ? 0
                  : (int)(0xFFFFFFFFu - (unsigned)(packed & 0xFFFFFFFFull));
    float qa = compute_q(beta[idx]);
    float xa[DIM];
    float b = 0.f;
#pragma unroll
    for (int k = 0; k < DIM; k++) {
        xa[k] = x[idx * DIM + k];
        b = fmaf(xa[k], xa[k], b);
    }
    g_rep[p * 3 + 0] = make_float4(-2.f * xa[0], -2.f * xa[1], -2.f * xa[2], -2.f * xa[3]);
    g_rep[p * 3 + 1] = make_float4(-2.f * xa[4], -2.f * xa[5], -2.f * xa[6], -2.f * xa[7]);
    g_rep[p * 3 + 2] = make_float4(b, qa, 0.f, 0.f);
}

// ---------------------------------------------------------------------------
// Kernel 3: main loop. One thread per hit, 511-cluster FMA loop with reps
// staged in shared memory. sqrt only when d2 < 1 (rare: P ~ 1.3e-4).
// Member cluster handled outside the loop (no compare in hot loop).
// ---------------------------------------------------------------------------
#define TPB 256

__global__ __launch_bounds__(TPB) void k_main(const float* __restrict__ beta,
                                              const float* __restrict__ x,
                                              const int* __restrict__ pid) {
    __shared__ float4 s_rep[NCLUST * 3];              // 24528 B
    for (int t = threadIdx.x; t < NCLUST * 3; t += TPB)
        s_rep[t] = g_rep[t];
    __syncthreads();

    int i = blockIdx.x * TPB + threadIdx.x;
    float contrib = 0.f;
    if (i < N_HITS) {
        float4 x0 = *(const float4*)(x + (size_t)i * DIM);
        float4 x1 = *(const float4*)(x + (size_t)i * DIM + 4);
        float xsq = x0.x * x0.x + x0.y * x0.y + x0.z * x0.z + x0.w * x0.w
                  + x1.x * x1.x + x1.y * x1.y + x1.z * x1.z + x1.w * x1.w;
        float q = compute_q(beta[i]);
        int p_own = pid[i];

        float rsum = 0.f;   // sum over all 511 clusters of hinge * q_a
#pragma unroll 4
        for (int p = 0; p < NCLUST; p++) {
            float4 ya0 = s_rep[p * 3 + 0];
            float4 ya1 = s_rep[p * 3 + 1];
            float4 bq  = s_rep[p * 3 + 2];
            float acc = xsq + bq.x;
            acc = fmaf(ya0.x, x0.x, acc);
            acc = fmaf(ya0.y, x0.y, acc);
            acc = fmaf(ya0.z, x0.z, acc);
            acc = fmaf(ya0.w, x0.w, acc);
            acc = fmaf(ya1.x, x1.x, acc);
            acc = fmaf(ya1.y, x1.y, acc);
            acc = fmaf(ya1.z, x1.z, acc);
            acc = fmaf(ya1.w, x1.w, acc);
            acc = fmaxf(acc, 0.f);            // dist_sq clamp (matches ref)
            if (acc < 1.f) {                  // hinge can be nonzero: rare
                float dist = sqrtf(fmaxf(acc, 1e-12f));
                rsum = fmaf(1.f - dist, bq.y, rsum);
            }
        }

        float total = 10.f * rsum;            // repulsive over ALL clusters

        if (p_own > 0) {                      // fix up own cluster
            int p = p_own - 1;
            float4 ya0 = s_rep[p * 3 + 0];
            float4 ya1 = s_rep[p * 3 + 1];
            float4 bq  = s_rep[p * 3 + 2];
            float acc = xsq + bq.x;
            acc = fmaf(ya0.x, x0.x, acc);
            acc = fmaf(ya0.y, x0.y, acc);
            acc = fmaf(ya0.z, x0.z, acc);
            acc = fmaf(ya0.w, x0.w, acc);
            acc = fmaf(ya1.x, x1.x, acc);
            acc = fmaf(ya1.y, x1.y, acc);
            acc = fmaf(ya1.z, x1.z, acc);
            acc = fmaf(ya1.w, x1.w, acc);
            acc = fmaxf(acc, 0.f);
            float dist = sqrtf(fmaxf(acc, 1e-12f));
            float hinge = fmaxf(1.f - dist, 0.f);
            // remove its repulsive term, add attractive term
            total += (acc - 10.f * hinge) * bq.y;
        }
        contrib = q * total;
    }

    // fp64 reduction: warp shuffle -> smem -> block -> one atomicAdd(double)
    double v = (double)contrib;
#pragma unroll
    for (int o = 16; o > 0; o >>= 1)
        v += __shfl_down_sync(0xffffffffu, v, o);

    __shared__ double s_part[TPB / 32];
    if ((threadIdx.x & 31) == 0) s_part[threadIdx.x >> 5] = v;
    __syncthreads();
    if (threadIdx.x < TPB / 32) {
        double w = s_part[threadIdx.x];
#pragma unroll
        for (int o = (TPB / 64); o > 0; o >>= 1)
            w += __shfl_down_sync(0xffu, w, o);
        if (threadIdx.x == 0) atomicAdd(&g_sum, w);
    }
}

// ---------------------------------------------------------------------------
// Kernel 4: finalize (mean over N axis)
// ---------------------------------------------------------------------------
__global__ void k_finalize(float* out) {
    out[0] = (float)(g_sum / (double)N_HITS);
}

// ---------------------------------------------------------------------------
// Launch: inputs in metadata order: w, beta, x, y, particle_id
// (w and y are unused by the reference loss)
// ---------------------------------------------------------------------------
extern "C" void kernel_launch(void* const* d_in, const int* in_sizes, int n_in,
                              void* d_out, int out_size) {
    const float* beta = (const float*)d_in[1];
    const float* x    = (const float*)d_in[2];
    const int*   pid  = (const int*)d_in[4];
    float* out = (float*)d_out;

    k_init<<<2, 256>>>();
    k_argmax<<<(N_HITS + 255) / 256, 256>>>(beta, pid);
    k_gather<<<2, 256>>>(beta, x);
    k_main<<<(N_HITS + TPB - 1) / TPB, TPB>>>(beta, x, pid);
    k_finalize<<<1, 1>>>(out);
}

// round 2
// speedup vs baseline: 1.1246x; 1.1246x over previous
#include <cuda_runtime.h>
#include <math.h>
#include <stdint.h>

// Problem constants (match reference_code)
#define N_HITS 200000
#define DIM 8
#define P_IDS 512
#define NCLUST 511          // nonzero particle ids 1..511
#define NPAIR 256           // 512 clusters (1 dummy pad) as 256 packed pairs
#define Q_MIN 0.01f

// ---------------------------------------------------------------------------
// Device scratch (no allocations allowed -> __device__ globals)
// ---------------------------------------------------------------------------
__device__ double g_sum;                           // static-init 0
__device__ unsigned long long g_best[P_IDS];       // packed (q_bits<<32)|(~idx); static-init 0
__device__ float g_q[N_HITS];                      // cached q per hit
// Pair-packed rep coefficients: for pair j (clusters 2j, 2j+1):
//   float index j*20 + 2*k + h, k=0..7 -> -2*xa_k ; k=8 -> |xa|^2 ; k=9 -> q_a
// Read in k_main as double2 (each double = one f32x2-packed coefficient pair).
__device__ __align__(16) float g_pairf[NPAIR * 20];

// ---------------------------------------------------------------------------
// Packed f32x2 helpers (sm_100+)
// ---------------------------------------------------------------------------
__device__ __forceinline__ unsigned long long fma2(unsigned long long a,
                                                   unsigned long long b,
                                                   unsigned long long c) {
    unsigned long long d;
    asm("fma.rn.f32x2 %0, %1, %2, %3;" : "=l"(d) : "l"(a), "l"(b), "l"(c));
    return d;
}
__device__ __forceinline__ unsigned long long add2(unsigned long long a,
                                                   unsigned long long b) {
    unsigned long long d;
    asm("add.rn.f32x2 %0, %1, %2;" : "=l"(d) : "l"(a), "l"(b));
    return d;
}
__device__ __forceinline__ unsigned long long bcast2(float x) {
    unsigned long long r;
    asm("mov.b64 %0, {%1, %2};" : "=l"(r) : "f"(x), "f"(x));
    return r;
}
__device__ __forceinline__ void unpack2(unsigned long long v, float& lo, float& hi) {
    asm("mov.b64 {%0, %1}, %2;" : "=f"(lo), "=f"(hi) : "l"(v));
}
__device__ __forceinline__ unsigned long long dbits(double d) {
    return __double_as_longlong(d);
}

__device__ __forceinline__ float compute_q(float beta) {
    float a = atanhf(beta);
    return fmaf(a, a, Q_MIN);
}

// ---------------------------------------------------------------------------
// Kernel 1: q cache + per-cluster argmax of q via packed atomicMax.
// q >= 0.01 > 0, so IEEE float bits are monotone as unsigned. Index stored
// complemented so q-ties pick the LOWER index (matches jnp.argmax).
// Requires g_best == 0 on entry (static init; re-zeroed by k_gather).
// ---------------------------------------------------------------------------
__global__ void k_argmax(const float* __restrict__ beta,
                         const int* __restrict__ pid) {
    int i = blockIdx.x * blockDim.x + threadIdx.x;
    if (i >= N_HITS) return;
    float q = compute_q(beta[i]);
    g_q[i] = q;
    int p = pid[i];
    if (p == 0) return;                       // noise hits excluded
    unsigned long long packed =
        ((unsigned long long)__float_as_uint(q) << 32) |
        (unsigned long long)(0xFFFFFFFFu - (unsigned)i);
    atomicMax(&g_best[p], packed);
}

// ---------------------------------------------------------------------------
// Kernel 2: gather reps into pair-packed layout; re-zero g_best (idempotence).
// Empty cluster -> packed==0 -> index 0 (matches jnp.argmax over all -inf).
// Thread 511 writes the dummy pad cluster (far away, q=0).
// ---------------------------------------------------------------------------
__global__ void k_gather(const float* __restrict__ x) {
    int p = blockIdx.x * blockDim.x + threadIdx.x;   // 0..511
    if (p >= P_IDS) return;
    int j = p >> 1, h = p & 1;
    float* dst = g_pairf + j * 20;
    if (p == NCLUST) {                               // dummy pad
#pragma unroll
        for (int k = 0; k < 8; k++) dst[2 * k + h] = 0.f;
        dst[16 + h] = 1e30f;                         // b huge -> never in hinge
        dst[18 + h] = 0.f;                           // q_a = 0
        return;
    }
    unsigned long long packed = g_best[p + 1];
    g_best[p + 1] = 0ull;                            // reset for next replay
    int idx = (packed == 0ull)
                  ? 0
                  : (int)(0xFFFFFFFFu - (unsigned)(packed & 0xFFFFFFFFull));
    float qa = g_q[idx];
    float b = 0.f;
#pragma unroll
    for (int k = 0; k < DIM; k++) {
        float v = x[idx * DIM + k];
        dst[2 * k + h] = -2.f * v;
        b = fmaf(v, v, b);
    }
    dst[16 + h] = b;
    dst[18 + h] = qa;
}

// ---------------------------------------------------------------------------
// Kernel 3: main loop. One thread per hit, 256 packed cluster-pair iterations
// with f32x2 FMAs. sqrt path only when min(dist_sq) < 1 (P ~ 1.3e-4/cluster).
// Member cluster handled outside the loop.
// ---------------------------------------------------------------------------
#define TPB 256

__global__ __launch_bounds__(TPB) void k_main(const float* __restrict__ x,
                                              const int* __restrict__ pid) {
    __shared__ __align__(16) float s_pairf[NPAIR * 20];   // 20480 B
    {
        const float4* src = (const float4*)g_pairf;
        float4* dst = (float4*)s_pairf;
        for (int t = threadIdx.x; t < NPAIR * 5; t += TPB) dst[t] = src[t];
    }
    __syncthreads();

    int i = blockIdx.x * TPB + threadIdx.x;
    float contrib = 0.f;
    if (i < N_HITS) {
        float4 x0 = *(const float4*)(x + (size_t)i * DIM);
        float4 x1 = *(const float4*)(x + (size_t)i * DIM + 4);
        float xsq = x0.x * x0.x + x0.y * x0.y + x0.z * x0.z + x0.w * x0.w
                  + x1.x * x1.x + x1.y * x1.y + x1.z * x1.z + x1.w * x1.w;
        float q = g_q[i];
        int p_own = pid[i];

        // Broadcast-packed hit coords (loop-invariant)
        unsigned long long xp0 = bcast2(x0.x), xp1 = bcast2(x0.y);
        unsigned long long xp2 = bcast2(x0.z), xp3 = bcast2(x0.w);
        unsigned long long xp4 = bcast2(x1.x), xp5 = bcast2(x1.y);
        unsigned long long xp6 = bcast2(x1.z), xp7 = bcast2(x1.w);
        unsigned long long xsqp = bcast2(xsq);

        const double2* sp = (const double2*)s_pairf;
        float rsum = 0.f;   // sum over clusters of hinge * q_a
#pragma unroll 4
        for (int j = 0; j < NPAIR; j++) {
            double2 c01 = sp[j * 5 + 0];
            double2 c23 = sp[j * 5 + 1];
            double2 c45 = sp[j * 5 + 2];
            double2 c67 = sp[j * 5 + 3];
            double2 cbq = sp[j * 5 + 4];
            unsigned long long acc = add2(xsqp, dbits(cbq.x));
            acc = fma2(dbits(c01.x), xp0, acc);
            acc = fma2(dbits(c01.y), xp1, acc);
            acc = fma2(dbits(c23.x), xp2, acc);
            acc = fma2(dbits(c23.y), xp3, acc);
            acc = fma2(dbits(c45.x), xp4, acc);
            acc = fma2(dbits(c45.y), xp5, acc);
            acc = fma2(dbits(c67.x), xp6, acc);
            acc = fma2(dbits(c67.y), xp7, acc);
            float lo, hi;
            unpack2(acc, lo, hi);
            if (fminf(lo, hi) < 1.0f) {       // rare (hinge active)
                float ql, qh;
                unpack2(dbits(cbq.y), ql, qh);
                if (lo < 1.0f)
                    rsum = fmaf(1.0f - sqrtf(fmaxf(lo, 1e-12f)), ql, rsum);
                if (hi < 1.0f)
                    rsum = fmaf(1.0f - sqrtf(fmaxf(hi, 1e-12f)), qh, rsum);
            }
        }

        float total = 10.f * rsum;            // repulsive over ALL clusters

        if (p_own > 0) {                      // own-cluster fixup
            int p = p_own - 1;
            const float* cf = s_pairf + (p >> 1) * 20 + (p & 1);
            float acc = xsq + cf[16];
            acc = fmaf(cf[0],  x0.x, acc);
            acc = fmaf(cf[2],  x0.y, acc);
            acc = fmaf(cf[4],  x0.z, acc);
            acc = fmaf(cf[6],  x0.w, acc);
            acc = fmaf(cf[8],  x1.x, acc);
            acc = fmaf(cf[10], x1.y, acc);
            acc = fmaf(cf[12], x1.z, acc);
            acc = fmaf(cf[14], x1.w, acc);
            float qa = cf[18];
            acc = fmaxf(acc, 0.f);            // dist_sq clamp (matches ref)
            float dist = sqrtf(fmaxf(acc, 1e-12f));
            float hinge = fmaxf(1.f - dist, 0.f);
            // remove its repulsive term, add attractive term
            total += (acc - 10.f * hinge) * qa;
        }
        contrib = q * total;
    }

    // fp64 reduction: warp shuffle -> smem -> block -> one atomicAdd(double)
    double v = (double)contrib;
#pragma unroll
    for (int o = 16; o > 0; o >>= 1)
        v += __shfl_down_sync(0xffffffffu, v, o);

    __shared__ double s_part[TPB / 32];
    if ((threadIdx.x & 31) == 0) s_part[threadIdx.x >> 5] = v;
    __syncthreads();
    if (threadIdx.x < TPB / 32) {
        double w = s_part[threadIdx.x];
#pragma unroll
        for (int o = (TPB / 64); o > 0; o >>= 1)
            w += __shfl_down_sync(0xffu, w, o);
        if (threadIdx.x == 0) atomicAdd(&g_sum, w);
    }
}

// ---------------------------------------------------------------------------
// Kernel 4: finalize (mean over N axis); re-zero g_sum for next replay.
// ---------------------------------------------------------------------------
__global__ void k_finalize(float* out) {
    out[0] = (float)(g_sum / (double)N_HITS);
    g_sum = 0.0;
}

// ---------------------------------------------------------------------------
// Launch: inputs in metadata order: w, beta, x, y, particle_id
// (w and y are unused by the reference loss)
// ---------------------------------------------------------------------------
extern "C" void kernel_launch(void* const* d_in, const int* in_sizes, int n_in,
                              void* d_out, int out_size) {
    const float* beta = (const float*)d_in[1];
    const float* x    = (const float*)d_in[2];
    const int*   pid  = (const int*)d_in[4];
    float* out = (float*)d_out;

    k_argmax<<<(N_HITS + 255) / 256, 256>>>(beta, pid);
    k_gather<<<1, 512>>>(x);
    k_main<<<(N_HITS + TPB - 1) / TPB, TPB>>>(x, pid);
    k_finalize<<<1, 1>>>(out);
}

// round 3
// speedup vs baseline: 1.4220x; 1.2645x over previous
#include <cuda_runtime.h>
#include <math.h>
#include <stdint.h>

// Problem constants (match reference_code)
#define N_HITS 200000
#define DIM 8
#define P_IDS 512
#define NCLUST 511          // nonzero particle ids 1..511
#define NPAIR 256           // 512 clusters (1 dummy pad) as 256 packed pairs
#define Q_MIN 0.01f

// ---------------------------------------------------------------------------
// Device scratch (no allocations allowed -> __device__ globals)
// ---------------------------------------------------------------------------
__device__ double g_sum;                           // static-init 0
__device__ unsigned long long g_best[P_IDS];       // packed (q_bits<<32)|(~idx)
__device__ float g_q[N_HITS];                      // cached q per hit
__device__ int g_done_a;                           // block counter (argmax)
__device__ int g_done_m;                           // block counter (main)
// Pair-packed coefficients: pair j (clusters 2j, 2j+1), stride 20 floats:
//   float j*20 + 2*k + h : k=0..7 -> -2*xa_k ; k=8 -> |xa|^2 ; 18..19 unused
__device__ __align__(16) float g_pairc[NPAIR * 20];
__device__ float g_qa[P_IDS];                      // q_alpha per cluster (pad=0)

// ---------------------------------------------------------------------------
// Packed f32x2 helpers (sm_100+)
// ---------------------------------------------------------------------------
typedef unsigned long long u64;
__device__ __forceinline__ u64 fma2(u64 a, u64 b, u64 c) {
    u64 d;
    asm("fma.rn.f32x2 %0, %1, %2, %3;" : "=l"(d) : "l"(a), "l"(b), "l"(c));
    return d;
}
__device__ __forceinline__ u64 add2(u64 a, u64 b) {
    u64 d;
    asm("add.rn.f32x2 %0, %1, %2;" : "=l"(d) : "l"(a), "l"(b));
    return d;
}
__device__ __forceinline__ u64 bcast2(float x) {
    u64 r;
    asm("mov.b64 %0, {%1, %2};" : "=l"(r) : "f"(x), "f"(x));
    return r;
}
__device__ __forceinline__ void unpack2(u64 v, float& lo, float& hi) {
    asm("mov.b64 {%0, %1}, %2;" : "=f"(lo), "=f"(hi) : "l"(v));
}
__device__ __forceinline__ u64 dbits(double d) { return __double_as_longlong(d); }

__device__ __forceinline__ float compute_q(float beta) {
    float a = atanhf(beta);
    return fmaf(a, a, Q_MIN);
}

// ---------------------------------------------------------------------------
// Kernel 1: q cache + per-cluster argmax via packed atomicMax; the LAST block
// then performs the representative gather (launch fusion).
// q >= 0.01 > 0 so float bits are monotone as unsigned; index complemented so
// q-ties pick the LOWER index (matches jnp.argmax). g_best==0 on entry
// (static init; re-zeroed in the gather phase each run).
// ---------------------------------------------------------------------------
#define ATPB 256

__global__ __launch_bounds__(ATPB) void k_argmax(const float* __restrict__ beta,
                                                 const int* __restrict__ pid,
                                                 const float* __restrict__ x) {
    int i = blockIdx.x * ATPB + threadIdx.x;
    if (i < N_HITS) {
        float q = compute_q(beta[i]);
        g_q[i] = q;
        int p = pid[i];
        if (p != 0) {
            u64 packed = ((u64)__float_as_uint(q) << 32) |
                         (u64)(0xFFFFFFFFu - (unsigned)i);
            atomicMax(&g_best[p], packed);
        }
    }
    // ---- last-block gather ----
    __threadfence();
    __syncthreads();
    __shared__ int s_last;
    if (threadIdx.x == 0)
        s_last = (atomicAdd(&g_done_a, 1) == (int)gridDim.x - 1);
    __syncthreads();
    if (!s_last) return;
    __threadfence();                                  // acquire

    for (int p = threadIdx.x; p < P_IDS; p += ATPB) { // p = cluster idx 0..511
        int j = p >> 1, h = p & 1;
        float* dst = g_pairc + j * 20;
        if (p == NCLUST) {                            // dummy pad cluster
#pragma unroll
            for (int k = 0; k < 8; k++) dst[2 * k + h] = 0.f;
            dst[16 + h] = 1e30f;                      // huge b -> hinge never
            g_qa[p] = 0.f;
            continue;
        }
        u64 packed = g_best[p + 1];
        g_best[p + 1] = 0ull;                         // reset for next replay
        int idx = (packed == 0ull)
                      ? 0
                      : (int)(0xFFFFFFFFu - (unsigned)(packed & 0xFFFFFFFFull));
        float b = 0.f;
#pragma unroll
        for (int k = 0; k < DIM; k++) {
            float v = x[idx * DIM + k];
            dst[2 * k + h] = -2.f * v;
            b = fmaf(v, v, b);
        }
        dst[16 + h] = b;
        g_qa[p] = g_q[idx];
    }
    if (threadIdx.x == 0) g_done_a = 0;               // reset counter
}

// ---------------------------------------------------------------------------
// Kernel 2: main loop. Each thread handles TWO hits against 256 packed
// cluster pairs (f32x2 FMAs). sqrt path only when any of the 4 dist_sq < 1
// (P ~ 1.3e-4 per pair). Own-cluster fixups outside the loop. LAST block
// writes the final scalar (launch fusion).
// ---------------------------------------------------------------------------
#define TPB 256
#define HPB (TPB * 2)

__global__ __launch_bounds__(TPB) void k_main(const float* __restrict__ x,
                                              const int* __restrict__ pid,
                                              float* __restrict__ out) {
    __shared__ __align__(16) float s_c[NPAIR * 20];   // 20480 B
    __shared__ float s_q[P_IDS];                      // 2048 B
    {
        const float4* src = (const float4*)g_pairc;
        float4* dst = (float4*)s_c;
        for (int t = threadIdx.x; t < NPAIR * 5; t += TPB) dst[t] = src[t];
        for (int t = threadIdx.x; t < P_IDS; t += TPB) s_q[t] = g_qa[t];
    }
    __syncthreads();

    int i0 = blockIdx.x * HPB + threadIdx.x;
    int i1 = i0 + TPB;
    // tail handling: clamp index, zero q/pid for invalid
    int i0c = i0 < N_HITS ? i0 : N_HITS - 1;
    int i1c = i1 < N_HITS ? i1 : N_HITS - 1;
    float q0 = (i0 < N_HITS) ? g_q[i0c] : 0.f;
    float q1 = (i1 < N_HITS) ? g_q[i1c] : 0.f;
    int pown0 = (i0 < N_HITS) ? pid[i0c] : 0;
    int pown1 = (i1 < N_HITS) ? pid[i1c] : 0;

    float4 a0 = *(const float4*)(x + (size_t)i0c * DIM);
    float4 a1 = *(const float4*)(x + (size_t)i0c * DIM + 4);
    float4 b0 = *(const float4*)(x + (size_t)i1c * DIM);
    float4 b1 = *(const float4*)(x + (size_t)i1c * DIM + 4);
    float xsqA = a0.x * a0.x + a0.y * a0.y + a0.z * a0.z + a0.w * a0.w
               + a1.x * a1.x + a1.y * a1.y + a1.z * a1.z + a1.w * a1.w;
    float xsqB = b0.x * b0.x + b0.y * b0.y + b0.z * b0.z + b0.w * b0.w
               + b1.x * b1.x + b1.y * b1.y + b1.z * b1.z + b1.w * b1.w;

    // Loop-invariant broadcast-packed hit coords
    u64 A0 = bcast2(a0.x), A1 = bcast2(a0.y), A2 = bcast2(a0.z), A3 = bcast2(a0.w);
    u64 A4 = bcast2(a1.x), A5 = bcast2(a1.y), A6 = bcast2(a1.z), A7 = bcast2(a1.w);
    u64 B0 = bcast2(b0.x), B1 = bcast2(b0.y), B2 = bcast2(b0.z), B3 = bcast2(b0.w);
    u64 B4 = bcast2(b1.x), B5 = bcast2(b1.y), B6 = bcast2(b1.z), B7 = bcast2(b1.w);
    u64 sqA = bcast2(xsqA), sqB = bcast2(xsqB);

    float rsumA = 0.f, rsumB = 0.f;   // sum_clusters hinge * q_a
#pragma unroll 2
    for (int j = 0; j < NPAIR; j++) {
        const float* base = s_c + j * 20;
        double2 c01 = *(const double2*)(base);
        double2 c23 = *(const double2*)(base + 4);
        double2 c45 = *(const double2*)(base + 8);
        double2 c67 = *(const double2*)(base + 12);
        u64 bp = *(const u64*)(base + 16);

        u64 accA = add2(sqA, bp);
        u64 accB = add2(sqB, bp);
        accA = fma2(dbits(c01.x), A0, accA);  accB = fma2(dbits(c01.x), B0, accB);
        accA = fma2(dbits(c01.y), A1, accA);  accB = fma2(dbits(c01.y), B1, accB);
        accA = fma2(dbits(c23.x), A2, accA);  accB = fma2(dbits(c23.x), B2, accB);
        accA = fma2(dbits(c23.y), A3, accA);  accB = fma2(dbits(c23.y), B3, accB);
        accA = fma2(dbits(c45.x), A4, accA);  accB = fma2(dbits(c45.x), B4, accB);
        accA = fma2(dbits(c45.y), A5, accA);  accB = fma2(dbits(c45.y), B5, accB);
        accA = fma2(dbits(c67.x), A6, accA);  accB = fma2(dbits(c67.x), B6, accB);
        accA = fma2(dbits(c67.y), A7, accA);  accB = fma2(dbits(c67.y), B7, accB);

        float la, ha, lb, hb;
        unpack2(accA, la, ha);
        unpack2(accB, lb, hb);
        float m = fminf(fminf(la, ha), fminf(lb, hb));
        if (m < 1.0f) {                        // rare (hinge active)
            float ql = s_q[2 * j], qh = s_q[2 * j + 1];
            if (la < 1.0f) rsumA = fmaf(1.0f - sqrtf(fmaxf(la, 1e-12f)), ql, rsumA);
            if (ha < 1.0f) rsumA = fmaf(1.0f - sqrtf(fmaxf(ha, 1e-12f)), qh, rsumA);
            if (lb < 1.0f) rsumB = fmaf(1.0f - sqrtf(fmaxf(lb, 1e-12f)), ql, rsumB);
            if (hb < 1.0f) rsumB = fmaf(1.0f - sqrtf(fmaxf(hb, 1e-12f)), qh, rsumB);
        }
    }

    float totalA = 10.f * rsumA;
    float totalB = 10.f * rsumB;

    if (pown0 > 0) {                           // own-cluster fixup, hit A
        int p = pown0 - 1;
        const float* cf = s_c + (p >> 1) * 20 + (p & 1);
        float acc = xsqA + cf[16];
        acc = fmaf(cf[0],  a0.x, acc); acc = fmaf(cf[2],  a0.y, acc);
        acc = fmaf(cf[4],  a0.z, acc); acc = fmaf(cf[6],  a0.w, acc);
        acc = fmaf(cf[8],  a1.x, acc); acc = fmaf(cf[10], a1.y, acc);
        acc = fmaf(cf[12], a1.z, acc); acc = fmaf(cf[14], a1.w, acc);
        acc = fmaxf(acc, 0.f);
        float dist = sqrtf(fmaxf(acc, 1e-12f));
        float hinge = fmaxf(1.f - dist, 0.f);
        totalA += (acc - 10.f * hinge) * s_q[p];
    }
    if (pown1 > 0) {                           // own-cluster fixup, hit B
        int p = pown1 - 1;
        const float* cf = s_c + (p >> 1) * 20 + (p & 1);
        float acc = xsqB + cf[16];
        acc = fmaf(cf[0],  b0.x, acc); acc = fmaf(cf[2],  b0.y, acc);
        acc = fmaf(cf[4],  b0.z, acc); acc = fmaf(cf[6],  b0.w, acc);
        acc = fmaf(cf[8],  b1.x, acc); acc = fmaf(cf[10], b1.y, acc);
        acc = fmaf(cf[12], b1.z, acc); acc = fmaf(cf[14], b1.w, acc);
        acc = fmaxf(acc, 0.f);
        float dist = sqrtf(fmaxf(acc, 1e-12f));
        float hinge = fmaxf(1.f - dist, 0.f);
        totalB += (acc - 10.f * hinge) * s_q[p];
    }

    // fp64 reduction: warp shuffle -> smem -> block -> one atomicAdd(double)
    double v = (double)(q0 * totalA) + (double)(q1 * totalB);
#pragma unroll
    for (int o = 16; o > 0; o >>= 1)
        v += __shfl_down_sync(0xffffffffu, v, o);

    __shared__ double s_part[TPB / 32];
    if ((threadIdx.x & 31) == 0) s_part[threadIdx.x >> 5] = v;
    __syncthreads();
    if (threadIdx.x == 0) {
        double w = 0.0;
#pragma unroll
        for (int k = 0; k < TPB / 32; k++) w += s_part[k];
        atomicAdd(&g_sum, w);
        // ---- last-block finalize ----
        if (atomicAdd(&g_done_m, 1) == (int)gridDim.x - 1) {
            double total = atomicAdd(&g_sum, 0.0);   // coherent read
            out[0] = (float)(total / (double)N_HITS);
            g_sum = 0.0;                              // reset for next replay
            g_done_m = 0;
        }
    }
}

// ---------------------------------------------------------------------------
// Launch: inputs in metadata order: w, beta, x, y, particle_id
// (w and y are unused by the reference loss)
// ---------------------------------------------------------------------------
extern "C" void kernel_launch(void* const* d_in, const int* in_sizes, int n_in,
                              void* d_out, int out_size) {
    const float* beta = (const float*)d_in[1];
    const float* x    = (const float*)d_in[2];
    const int*   pid  = (const int*)d_in[4];
    float* out = (float*)d_out;

    k_argmax<<<(N_HITS + ATPB - 1) / ATPB, ATPB>>>(beta, pid, x);
    k_main<<<(N_HITS + HPB - 1) / HPB, TPB>>>(x, pid, out);
}